// round 2
// baseline (speedup 1.0000x reference)
#include <cuda_runtime.h>
#include <math.h>
#include <stdint.h>

// ---------------------------------------------------------------------------
// ImportanceRenderer: two-pass NeRF-style renderer.
//  K0: transpose planes (B,3,32,256,256) -> channel-last (B,3,256,256,32)
//  K1: coarse model eval (tri-plane bilinear + MLP) -> rgb_c, sigma_c(=sdf out)
//  K2: per-ray coarse march + importance inverse-CDF sampling -> fine depths
//  K3: fine model eval -> rgb_f, sigma_f
//  K4: per-ray merge (two sorted lists) + final 96-sample march -> outputs
// ---------------------------------------------------------------------------

#define B_N 2
#define R_N 4096
#define SC 48
#define SF 48
#define NRAY (B_N * R_N)        // 8192
#define NSAMP (NRAY * SC)       // 393216
#define CPL 32
#define HPX 256
#define HID 64
#define CRGB 32
#define PLSTRIDE (HPX * HPX * CPL)   // floats per plane, channel-last

#define RAY_START_F 2.25f
#define DELTA_F (1.05f / 47.0f)

#define OFF_DEPTH (NRAY * CRGB)         // 262144
#define OFF_WSUM  (OFF_DEPTH + NRAY)    // 270336
#define OFF_SDF   (OFF_WSUM + NRAY)     // 278528

// Scratch (static device allocations; no cudaMalloc allowed)
__device__ float g_planesT[6 * PLSTRIDE];           // 50.3 MB
__device__ float g_rgb_c[(size_t)NSAMP * CRGB];     // 50.3 MB
__device__ float g_rgb_f[(size_t)NSAMP * CRGB];     // 50.3 MB
__device__ float g_sig_f[NSAMP];
__device__ float g_zf[NSAMP];

__device__ __forceinline__ float softplus_f(float x) {
    // jax.nn.softplus = logaddexp(x, 0) = max(x,0) + log1p(exp(-|x|))
    return fmaxf(x, 0.f) + log1pf(expf(-fabsf(x)));
}
__device__ __forceinline__ float sigmoid_f(float x) {
    return 1.f / (1.f + expf(-x));
}
__device__ __forceinline__ float zc_depth(int i) {
    return RAY_START_F + ((float)i + 0.5f) * DELTA_F;
}

// ---------------------------------------------------------------------------
// K0: tiled transpose (C=32) x (HW=65536) -> (HW) x (C), per plane
// ---------------------------------------------------------------------------
__global__ void transpose_planes_kernel(const float* __restrict__ in) {
    __shared__ float tile[32][33];
    int p = blockIdx.y;                 // 0..5 (B*3 planes)
    int hw0 = blockIdx.x * 32;
    int tx = threadIdx.x;               // 0..31
    int ty = threadIdx.y;               // 0..7
    const float* ip = in + (size_t)p * CPL * (HPX * HPX);
    float* op = g_planesT + (size_t)p * PLSTRIDE;
    #pragma unroll
    for (int c = ty; c < 32; c += 8)
        tile[c][tx] = ip[(size_t)c * (HPX * HPX) + hw0 + tx];
    __syncthreads();
    #pragma unroll
    for (int r = ty; r < 32; r += 8)
        op[(size_t)(hw0 + r) * 32 + tx] = tile[tx][r];
}

// ---------------------------------------------------------------------------
// Bilinear sample of one channel (lane) from a channel-last plane.
// Matches reference: zero outside [0,W), clip-then-gather indices.
// ---------------------------------------------------------------------------
__device__ __forceinline__ float bilin_ch(const float* __restrict__ p,
                                          float u, float v, int lane) {
    float x = ((u + 1.f) * 256.f - 1.f) * 0.5f;
    float y = ((v + 1.f) * 256.f - 1.f) * 0.5f;
    float x0f = floorf(x), y0f = floorf(y);
    float wx = x - x0f, wy = y - y0f;
    float x1f = x0f + 1.f, y1f = y0f + 1.f;
    int x0 = (int)fminf(fmaxf(x0f, 0.f), 255.f);
    int x1 = (int)fminf(fmaxf(x1f, 0.f), 255.f);
    int y0 = (int)fminf(fmaxf(y0f, 0.f), 255.f);
    int y1 = (int)fminf(fmaxf(y1f, 0.f), 255.f);
    bool vx0 = (x0f >= 0.f) && (x0f < 256.f);
    bool vx1 = (x1f >= 0.f) && (x1f < 256.f);
    bool vy0 = (y0f >= 0.f) && (y0f < 256.f);
    bool vy1 = (y1f >= 0.f) && (y1f < 256.f);
    float w00 = (vx0 && vy0) ? (1.f - wx) * (1.f - wy) : 0.f;
    float w01 = (vx1 && vy0) ? wx * (1.f - wy) : 0.f;
    float w10 = (vx0 && vy1) ? (1.f - wx) * wy : 0.f;
    float w11 = (vx1 && vy1) ? wx * wy : 0.f;
    const float* r0 = p + (size_t)(y0 * 256) * 32;
    const float* r1 = p + (size_t)(y1 * 256) * 32;
    float v00 = __ldg(r0 + x0 * 32 + lane);
    float v01 = __ldg(r0 + x1 * 32 + lane);
    float v10 = __ldg(r1 + x0 * 32 + lane);
    float v11 = __ldg(r1 + x1 * 32 + lane);
    return v00 * w00 + v01 * w01 + v10 * w10 + v11 * w11;
}

// ---------------------------------------------------------------------------
// K1/K3: model eval. PASS=0 coarse (analytic depths, sigma->d_out sdf region),
// PASS=1 fine (depths from g_zf, sigma->g_sig_f).
// Block = 128 threads = 128 samples. Gather phase: warp-cooperative,
// lane = channel (coalesced 128B loads). MLP phase: thread = sample,
// weights in shared (transposed w1 for float4 LDS).
// ---------------------------------------------------------------------------
template <int PASS>
__global__ __launch_bounds__(128)
void eval_kernel(const float* __restrict__ origins,
                 const float* __restrict__ dirs,
                 const float* __restrict__ w1, const float* __restrict__ b1,
                 const float* __restrict__ w2, const float* __restrict__ b2,
                 float* __restrict__ sig_out_coarse) {
    __shared__ __align__(16) float s_w1t[HID * CPL];   // [j][c]
    __shared__ __align__(16) float s_w2[HID * 36];     // [j][k], padded to 36
    __shared__ float s_b1[HID];
    __shared__ float s_b2[36];
    __shared__ float s_feat[128 * 33];

    int tid = threadIdx.x;
    for (int i = tid; i < HID * CPL; i += 128) {
        int j = i >> 5, c = i & 31;
        s_w1t[i] = w1[c * HID + j];
    }
    for (int i = tid; i < HID * 36; i += 128) {
        int j = i / 36, k = i - j * 36;
        s_w2[i] = (k < 33) ? w2[j * 33 + k] : 0.f;
    }
    if (tid < HID) s_b1[tid] = b1[tid];
    if (tid < 36) s_b2[tid] = (tid < 33) ? b2[tid] : 0.f;

    int lane = tid & 31;
    int warp = tid >> 5;
    int base_sample = blockIdx.x * 128 + warp * 32;

    // ---- Gather phase: 32 samples per warp, lane = channel ----
    for (int s = 0; s < 32; s++) {
        int gs = base_sample + s;
        int samp = gs % SC;
        int ray = gs / SC;
        float t;
        if (PASS == 0) t = zc_depth(samp);
        else t = __ldg(&g_zf[gs]);
        float ox = __ldg(&origins[ray * 3 + 0]);
        float oy = __ldg(&origins[ray * 3 + 1]);
        float oz = __ldg(&origins[ray * 3 + 2]);
        float dx = __ldg(&dirs[ray * 3 + 0]);
        float dy = __ldg(&dirs[ray * 3 + 1]);
        float dz = __ldg(&dirs[ray * 3 + 2]);
        float X = ox + t * dx, Y = oy + t * dy, Z = oz + t * dz;
        int bb = ray >> 12;  // /R_N
        const float* pb = g_planesT + (size_t)(bb * 3) * PLSTRIDE;
        // plane0: (x,y); plane1: (x,z); plane2: (z,x)
        float acc = bilin_ch(pb, X, Y, lane);
        acc += bilin_ch(pb + PLSTRIDE, X, Z, lane);
        acc += bilin_ch(pb + 2 * PLSTRIDE, Z, X, lane);
        s_feat[(warp * 32 + s) * 33 + lane] = acc * (1.f / 3.f);
    }
    __syncthreads();

    // ---- MLP phase: thread = sample ----
    float feat[CPL];
    #pragma unroll
    for (int c = 0; c < CPL; c++) feat[c] = s_feat[tid * 33 + c];
    float acc[36];
    #pragma unroll
    for (int k = 0; k < 36; k++) acc[k] = s_b2[k];
    const float4* w1t4 = reinterpret_cast<const float4*>(s_w1t);
    const float4* w24 = reinterpret_cast<const float4*>(s_w2);
    for (int j = 0; j < HID; j++) {
        float h = s_b1[j];
        #pragma unroll
        for (int cc = 0; cc < 8; cc++) {
            float4 wv = w1t4[j * 8 + cc];
            h += feat[4 * cc + 0] * wv.x + feat[4 * cc + 1] * wv.y +
                 feat[4 * cc + 2] * wv.z + feat[4 * cc + 3] * wv.w;
        }
        h = softplus_f(h);
        #pragma unroll
        for (int kk = 0; kk < 9; kk++) {
            float4 wv = w24[j * 9 + kk];
            acc[4 * kk + 0] += h * wv.x;
            acc[4 * kk + 1] += h * wv.y;
            acc[4 * kk + 2] += h * wv.z;
            acc[4 * kk + 3] += h * wv.w;
        }
    }
    int gid = blockIdx.x * 128 + tid;
    if (PASS == 0) sig_out_coarse[gid] = acc[0];
    else g_sig_f[gid] = acc[0];

    __syncthreads();  // safe to reuse s_feat
    #pragma unroll
    for (int k = 0; k < CRGB; k++)
        s_feat[tid * 33 + k] = sigmoid_f(acc[1 + k]) * 1.002f - 0.001f;
    __syncthreads();
    float* ro = (PASS == 0) ? g_rgb_c : g_rgb_f;
    size_t ob = (size_t)blockIdx.x * 128 * CRGB;
    for (int i = tid; i < 128 * CRGB; i += 128) {
        int sm = i >> 5, k = i & 31;
        ro[ob + i] = s_feat[sm * 33 + k];
    }
}

// ---------------------------------------------------------------------------
// K2: per-ray coarse march -> weights -> smoothed PDF -> inverse-CDF sampling.
// One thread per ray.
// ---------------------------------------------------------------------------
__global__ void importance_kernel(const float* __restrict__ sdf) {
    int ray = blockIdx.x * blockDim.x + threadIdx.x;
    if (ray >= NRAY) return;
    const float* sg = sdf + (size_t)ray * SC;

    float w[SC - 1];  // 47 coarse weights
    float T = 1.f;
    float prev = __ldg(&sg[0]);
    for (int i = 0; i < SC - 1; i++) {
        float cur = __ldg(&sg[i + 1]);
        float dens = softplus_f(0.5f * (prev + cur) - 1.f);
        float a = 1.f - expf(-dens * DELTA_F);
        w[i] = a * T;
        T *= (1.f - a + 1e-10f);
        prev = cur;
    }
    // wp = [0, w0..w46, 0]; wmax[i]=max(wp[i],wp[i+1]); w2[i]=0.5*(wmax[i]+wmax[i+1])+0.01
    // used weights: w2[1..45] (45 values); bins: z_mid[0..46]
    float pw[45];
    float sum = 0.f;
    for (int i = 1; i <= 45; i++) {
        float wp_i  = (i >= 1 && i <= 47) ? w[i - 1] : 0.f;
        float wp_i1 = (i + 1 >= 1 && i + 1 <= 47) ? w[i] : 0.f;
        float wp_i2 = (i + 2 <= 47) ? w[i + 1] : 0.f;
        float wm0 = fmaxf(wp_i, wp_i1);
        float wm1 = fmaxf(wp_i1, wp_i2);
        float val = 0.5f * (wm0 + wm1) + 0.01f;
        pw[i - 1] = val;
        sum += val;
    }
    float cdf[46];
    cdf[0] = 0.f;
    for (int i = 0; i < 45; i++) cdf[i + 1] = cdf[i] + pw[i] / sum;

    int idx = 0;
    for (int j = 0; j < SF; j++) {
        float u = (float)j / 47.0f;
        while (idx < 46 && cdf[idx] <= u) idx++;  // searchsorted right
        int below = idx - 1;
        below = below < 0 ? 0 : (below > 45 ? 45 : below);
        int above = idx > 45 ? 45 : idx;
        float cb = cdf[below], ca = cdf[above];
        float bb = 0.5f * (zc_depth(below) + zc_depth(below + 1));
        float ba = 0.5f * (zc_depth(above) + zc_depth(above + 1));
        float d = ca - cb;
        float denom = (d < 1e-5f) ? 1.f : d;
        g_zf[(size_t)ray * SF + j] = bb + (u - cb) / denom * (ba - bb);
    }
}

// ---------------------------------------------------------------------------
// K4: per-ray merge of sorted coarse (analytic) + fine depths, final march.
// Warp per ray, lane = channel.
// ---------------------------------------------------------------------------
__global__ __launch_bounds__(128)
void finalize_kernel(const float* __restrict__ sdfc, float* __restrict__ out) {
    __shared__ float s_zf[4][SF], s_sc[4][SC], s_sf[4][SF];
    int lane = threadIdx.x & 31;
    int wp = threadIdx.x >> 5;
    int ray = blockIdx.x * 4 + wp;
    for (int i = lane; i < SC; i += 32) {
        s_zf[wp][i] = g_zf[(size_t)ray * SF + i];
        s_sc[wp][i] = sdfc[(size_t)ray * SC + i];
        s_sf[wp][i] = g_sig_f[(size_t)ray * SF + i];
    }
    __syncwarp();

    int ic = 0, ifn = 0;
    float T = 1.f, rgb_acc = 0.f, dep = 0.f, ws = 0.f;
    float zp, sp2, cp;
    // first sample (stable tie-break: coarse first, matching argsort of [coarse,fine])
    {
        bool tc = (zc_depth(0) <= s_zf[wp][0]);
        if (tc) {
            zp = zc_depth(0); sp2 = s_sc[wp][0];
            cp = __ldg(&g_rgb_c[((size_t)ray * SC + 0) * CRGB + lane]);
            ic = 1;
        } else {
            zp = s_zf[wp][0]; sp2 = s_sf[wp][0];
            cp = __ldg(&g_rgb_f[((size_t)ray * SF + 0) * CRGB + lane]);
            ifn = 1;
        }
    }
    for (int i = 1; i < SC + SF; i++) {
        bool tc = (ic < SC) && (ifn >= SF || zc_depth(ic) <= s_zf[wp][ifn]);
        float z, sgv, cc;
        if (tc) {
            z = zc_depth(ic); sgv = s_sc[wp][ic];
            cc = __ldg(&g_rgb_c[((size_t)ray * SC + ic) * CRGB + lane]);
            ic++;
        } else {
            z = s_zf[wp][ifn]; sgv = s_sf[wp][ifn];
            cc = __ldg(&g_rgb_f[((size_t)ray * SF + ifn) * CRGB + lane]);
            ifn++;
        }
        float delta = z - zp;
        float cmid = 0.5f * (cp + cc);
        float smid = softplus_f(0.5f * (sp2 + sgv) - 1.f);
        float a = 1.f - expf(-smid * delta);
        float wgt = a * T;
        T *= (1.f - a + 1e-10f);
        rgb_acc += wgt * cmid;
        dep += wgt * 0.5f * (zp + z);
        ws += wgt;
        zp = z; sp2 = sgv; cp = cc;
    }
    out[(size_t)ray * CRGB + lane] = rgb_acc * 2.f - 1.f;
    if (lane == 0) {
        out[OFF_DEPTH + ray] = dep;
        out[OFF_WSUM + ray] = ws;
    }
}

// ---------------------------------------------------------------------------
extern "C" void kernel_launch(void* const* d_in, const int* in_sizes, int n_in,
                              void* d_out, int out_size) {
    const float* planes = (const float*)d_in[0];
    const float* org    = (const float*)d_in[1];
    const float* dir    = (const float*)d_in[2];
    const float* w1     = (const float*)d_in[3];
    const float* b1     = (const float*)d_in[4];
    const float* w2     = (const float*)d_in[5];
    const float* b2     = (const float*)d_in[6];
    float* out = (float*)d_out;

    // K0: channel-last transpose of planes
    {
        dim3 tb(32, 8), tg(HPX * HPX / 32, 6);
        transpose_planes_kernel<<<tg, tb>>>(planes);
    }
    // K1: coarse eval (sigma -> sdf output region)
    eval_kernel<0><<<NSAMP / 128, 128>>>(org, dir, w1, b1, w2, b2, out + OFF_SDF);
    // K2: importance sampling
    importance_kernel<<<(NRAY + 127) / 128, 128>>>(out + OFF_SDF);
    // K3: fine eval
    eval_kernel<1><<<NSAMP / 128, 128>>>(org, dir, w1, b1, w2, b2, nullptr);
    // K4: merge + final march
    finalize_kernel<<<NRAY / 4, 128>>>(out + OFF_SDF, out);
}